// round 17
// baseline (speedup 1.0000x reference)
#include <cuda_runtime.h>

// Dynamic local filtering: out[n,c,h,w] = sum_{k1,k2} x_pad[n,c,h+k1,w+k2] * kern[n,(c*25+k1*5+k2),h,w]
// then leaky_relu(0.2). Replicate padding. Shapes fixed: N=4, C=8, H=W=256, K=5.
// R11: persistent grid-stride version of the R6 champion (full-width 256x4 tiles,
//      4px/thread LDG.128 contiguous 4KB/tap, split 13/12 preload). Each CTA
//      loops over tiles so tile i+1's batch-A loads issue right after tile i's
//      FMAs -> no inter-tile/wave dead time in the DRAM request stream.

#define WID 256
#define HEI 256
#define HW  (WID * HEI)
#define TH  4     // rows per tile
#define SW  (WID + 4)  // 260 floats per smem row (float4-aligned)
#define SH  (TH + 4)   // 8
#define NTILES (32 * (HEI / TH))   // 32 planes x 64 row-tiles = 2048

__global__ __launch_bounds__(256)
void dynconv5x5_kernel(const float* __restrict__ x,
                       const float* __restrict__ kern,
                       float* __restrict__ out)
{
    __shared__ float tile[SH * SW];

    const int tid = threadIdx.x;            // 0..255
    const int lx = tid & 63;                // 64 threads across the row
    const int ly = tid >> 6;                // 4 rows
    const int w0 = lx * 4;                  // first of 4 pixels handled

    for (int t_idx = blockIdx.x; t_idx < NTILES; t_idx += gridDim.x) {
        const int plane = t_idx >> 6;       // n*C + c, 0..31
        const int by = (t_idx & 63) * TH;
        const int h  = by + ly;

        // Weight pointer: per tap t, this thread's 4 pixels' weights are one float4.
        const float4* __restrict__ k4 = (const float4*)kern
            + (size_t)plane * 25 * (HW / 4)
            + (size_t)(h * WID + w0) / 4;

        // ---- Batch A: issue taps 0..12 (13 LDG.128 in flight) ----
        float4 kv[13];
        #pragma unroll
        for (int t = 0; t < 13; t++) {
            kv[t] = __ldcs(&k4[(size_t)t * (HW / 4)]);
        }

        // Protect smem tile from the previous iteration's readers, then fill.
        __syncthreads();
        const float* __restrict__ xp = x + (size_t)plane * HW;
        #pragma unroll
        for (int i = tid; i < SH * SW; i += 256) {
            int sy = i / SW;
            int sx = i - sy * SW;
            int gy = by + sy - 2; gy = max(0, min(HEI - 1, gy));
            int gx = sx - 2;      gx = max(0, min(WID - 1, gx));
            tile[i] = xp[gy * WID + gx];
        }
        __syncthreads();

        // Stage the 8-wide x windows for all 5 dy rows (smem -> regs).
        float s[5][8];
        #pragma unroll
        for (int dy = 0; dy < 5; dy++) {
            const float4* srow = (const float4*)&tile[(ly + dy) * SW + w0];
            float4 s0 = srow[0];
            float4 s1 = srow[1];
            s[dy][0] = s0.x; s[dy][1] = s0.y; s[dy][2] = s0.z; s[dy][3] = s0.w;
            s[dy][4] = s1.x; s[dy][5] = s1.y; s[dy][6] = s1.z; s[dy][7] = s1.w;
        }

        // ---- Batch B issue overlapped with batch A consumption ----
        asm volatile("" ::: "memory");
        float4 kv2[12];
        #pragma unroll
        for (int t = 0; t < 12; t++) {
            kv2[t] = __ldcs(&k4[(size_t)(t + 13) * (HW / 4)]);
        }

        float ax = 0.f, ay = 0.f, az = 0.f, aw = 0.f;

        #pragma unroll
        for (int t = 0; t < 13; t++) {
            int dy = t / 5, dx = t % 5;
            float4 w = kv[t];
            ax += w.x * s[dy][dx + 0];
            ay += w.y * s[dy][dx + 1];
            az += w.z * s[dy][dx + 2];
            aw += w.w * s[dy][dx + 3];
        }

        #pragma unroll
        for (int t = 13; t < 25; t++) {
            int dy = t / 5, dx = t % 5;
            float4 w = kv2[t - 13];
            ax += w.x * s[dy][dx + 0];
            ay += w.y * s[dy][dx + 1];
            az += w.z * s[dy][dx + 2];
            aw += w.w * s[dy][dx + 3];
        }

        // leaky_relu(0.2)
        ax = ax >= 0.f ? ax : 0.2f * ax;
        ay = ay >= 0.f ? ay : 0.2f * ay;
        az = az >= 0.f ? az : 0.2f * az;
        aw = aw >= 0.f ? aw : 0.2f * aw;

        float4 r = make_float4(ax, ay, az, aw);
        __stcs(&((float4*)out)[(size_t)plane * (HW / 4) + (size_t)(h * WID + w0) / 4], r);
        // Loop: next tile's batch-A loads issue immediately (before the sync),
        // keeping the DRAM request stream continuous across tiles.
    }
}

extern "C" void kernel_launch(void* const* d_in, const int* in_sizes, int n_in,
                              void* d_out, int out_size)
{
    const float* x    = (const float*)d_in[0];   // (4, 8, 256, 256)
    const float* kern = (const float*)d_in[1];   // (4, 200, 256, 256)
    float* out = (float*)d_out;                  // (4, 8, 256, 256)

    static int nctas = 0;
    if (nctas == 0) {
        int dev = 0, sms = 148;
        cudaGetDevice(&dev);
        cudaDeviceGetAttribute(&sms, cudaDevAttrMultiProcessorCount, dev);
        nctas = sms * 3;                         // 3 CTAs/SM (regs ~70 -> fits)
        if (nctas > NTILES) nctas = NTILES;
    }

    dim3 block(256, 1, 1);
    dim3 grid(nctas, 1, 1);
    dynconv5x5_kernel<<<grid, block>>>(x, kern, out);
}